// round 13
// baseline (speedup 1.0000x reference)
#include <cuda_runtime.h>
#include <cstdint>

#define NN    20000
#define EE    320000
#define E2T   340000          // EE + NN self loops
#define HIDC  256
#define NH    4
#define NEG   0.2f

// ---------------- device scratch (static, no allocation) ----------------
__device__ __align__(16) float g_xl[NN * HIDC];
__device__ __align__(16) float g_xr[NN * HIDC];
__device__ __align__(16) float g_h [NN * HIDC];
__device__ int g_cnt[NN];
__device__ int g_off[NN + 1];
__device__ int g_cur[NN];
__device__ int g_srcs[E2T];
__device__ int g_ctr[2];          // dynamic work tickets, one per layer

// packed fp32 FMA
__device__ __forceinline__ void ffma2(uint64_t& d, uint64_t a, uint64_t b) {
    asm("fma.rn.f32x2 %0, %1, %2, %0;" : "+l"(d) : "l"(a), "l"(b));
}
__device__ __forceinline__ uint64_t fma2v(uint64_t a, uint64_t b, uint64_t c) {
    uint64_t d;
    asm("fma.rn.f32x2 %0, %1, %2, %3;" : "=l"(d) : "l"(a), "l"(b), "l"(c));
    return d;
}
__device__ __forceinline__ float2 unpack2(uint64_t v) {
    uint32_t lo, hi;
    asm("mov.b64 {%0, %1}, %2;" : "=r"(lo), "=r"(hi) : "l"(v));
    return make_float2(__uint_as_float(lo), __uint_as_float(hi));
}
__device__ __forceinline__ uint64_t pack2(float x) {
    uint64_t d;
    asm("mov.b64 %0, {%1, %1};" : "=l"(d) : "r"(__float_as_uint(x)));
    return d;
}
#define C_ONE2  0x3F8000003F800000ull   // (1.0f, 1.0f)
#define C_06    0x3F19999A3F19999Aull   // (0.6f, 0.6f)
#define C_04    0x3ECCCCCD3ECCCCCDull   // (0.4f, 0.4f)
#define C_ABS   0x7FFFFFFF7FFFFFFFull

// ---------------- fused dual GEMM (xl & xr), fp32 via fma.rn.f32x2 ----------------
// CTA tile 96(M) x 128(N), 256 threads, 6x8 outputs/thread.
__global__ void __launch_bounds__(256, 2)
gemm_dual(const float* __restrict__ Ain, int a_is_gh,
          const float* __restrict__ Wl, const float* __restrict__ bl,
          const float* __restrict__ Wr, const float* __restrict__ br) {
    __shared__ float As[16][100];   // [k][m] 96 + pad 4
    __shared__ float Bs[16][136];   // [k][n] 128 + pad 8

    const float* A = a_is_gh ? g_h : Ain;
    int by = blockIdx.y;
    int sel = by >> 1;
    const float* W    = sel ? Wr : Wl;
    const float* bias = sel ? br : bl;
    float*       C    = sel ? g_xr : g_xl;
    int bn = (by & 1) * 128;
    int bm = blockIdx.x * 96;

    int tid = threadIdx.x;
    int tx = tid & 15, ty = tid >> 4;
    bool aload = tid < 192;
    int e0 = tid * 2, e1 = tid * 2 + 1;
    int r0 = e0 >> 2, q0 = e0 & 3;
    int r1 = e1 >> 2, q1 = e1 & 3;
    int w_r = tid >> 4, w_c = tid & 15;

    uint64_t acc[6][4];
    #pragma unroll
    for (int i = 0; i < 6; i++)
        #pragma unroll
        for (int q = 0; q < 4; q++) acc[i][q] = 0ull;

    float4 pa0 = make_float4(0.f, 0.f, 0.f, 0.f);
    float4 pa1 = make_float4(0.f, 0.f, 0.f, 0.f);
    float4 pb[2];
    if (aload) {
        if (bm + r0 < NN) pa0 = *(const float4*)(A + (size_t)(bm + r0) * 256 + q0 * 4);
        if (bm + r1 < NN) pa1 = *(const float4*)(A + (size_t)(bm + r1) * 256 + q1 * 4);
    }
    #pragma unroll
    for (int h = 0; h < 2; h++)
        pb[h] = *(const float4*)(W + (size_t)w_r * 256 + bn + h * 64 + w_c * 4);

    for (int k0 = 0; k0 < 256; k0 += 16) {
        if (aload) {
            As[q0 * 4 + 0][r0] = pa0.x;
            As[q0 * 4 + 1][r0] = pa0.y;
            As[q0 * 4 + 2][r0] = pa0.z;
            As[q0 * 4 + 3][r0] = pa0.w;
            As[q1 * 4 + 0][r1] = pa1.x;
            As[q1 * 4 + 1][r1] = pa1.y;
            As[q1 * 4 + 2][r1] = pa1.z;
            As[q1 * 4 + 3][r1] = pa1.w;
        }
        #pragma unroll
        for (int h = 0; h < 2; h++)
            *(float4*)&Bs[w_r][h * 64 + w_c * 4] = pb[h];
        __syncthreads();

        if (k0 < 240) {
            int kn = k0 + 16;
            if (aload) {
                if (bm + r0 < NN)
                    pa0 = *(const float4*)(A + (size_t)(bm + r0) * 256 + kn + q0 * 4);
                if (bm + r1 < NN)
                    pa1 = *(const float4*)(A + (size_t)(bm + r1) * 256 + kn + q1 * 4);
            }
            #pragma unroll
            for (int h = 0; h < 2; h++)
                pb[h] = *(const float4*)(W + (size_t)(kn + w_r) * 256 + bn + h * 64 + w_c * 4);
        }

        #pragma unroll
        for (int k = 0; k < 16; k++) {
            float2 af0 = *(const float2*)&As[k][ty * 6];
            float2 af1 = *(const float2*)&As[k][ty * 6 + 2];
            float2 af2 = *(const float2*)&As[k][ty * 6 + 4];
            ulonglong2 u = *(const ulonglong2*)&Bs[k][tx * 4];
            ulonglong2 v = *(const ulonglong2*)&Bs[k][64 + tx * 4];
            uint64_t ar[6];
            ar[0] = pack2(af0.x); ar[1] = pack2(af0.y);
            ar[2] = pack2(af1.x); ar[3] = pack2(af1.y);
            ar[4] = pack2(af2.x); ar[5] = pack2(af2.y);
            #pragma unroll
            for (int i = 0; i < 6; i++) {
                ffma2(acc[i][0], ar[i], u.x);
                ffma2(acc[i][1], ar[i], u.y);
                ffma2(acc[i][2], ar[i], v.x);
                ffma2(acc[i][3], ar[i], v.y);
            }
        }
        __syncthreads();
    }

    float4 bv0 = *(const float4*)(bias + bn + tx * 4);
    float4 bv1 = *(const float4*)(bias + bn + 64 + tx * 4);
    #pragma unroll
    for (int i = 0; i < 6; i++) {
        int row = bm + ty * 6 + i;
        if (row < NN) {
            float2 c0 = unpack2(acc[i][0]), c1 = unpack2(acc[i][1]);
            float2 c2 = unpack2(acc[i][2]), c3 = unpack2(acc[i][3]);
            *(float4*)(C + (size_t)row * 256 + bn + tx * 4) =
                make_float4(c0.x + bv0.x, c0.y + bv0.y, c1.x + bv0.z, c1.y + bv0.w);
            *(float4*)(C + (size_t)row * 256 + bn + 64 + tx * 4) =
                make_float4(c2.x + bv1.x, c2.y + bv1.y, c3.x + bv1.z, c3.y + bv1.w);
        }
    }
}

// ---------------- CSR build (once per launch; edges shared by both layers) ----
__global__ void hist_init_k() {
    int i = blockIdx.x * blockDim.x + threadIdx.x;
    if (i < NN) g_cnt[i] = 1;      // self loop pre-counted
    if (i < 2)  g_ctr[i] = 0;
}
__global__ void hist_k(const int* __restrict__ ei) {
    int e = blockIdx.x * blockDim.x + threadIdx.x;
    if (e < EE) atomicAdd(&g_cnt[ei[EE + e]], 1);
}
__global__ void scan_k() {
    __shared__ int sums[1024];
    int t = threadIdx.x;
    int base = t * 20;
    int s = 0;
    if (t < 1000) {
        #pragma unroll
        for (int i = 0; i < 20; i++) s += g_cnt[base + i];
    }
    sums[t] = s;
    __syncthreads();
    #pragma unroll
    for (int d = 1; d < 1024; d <<= 1) {
        int v = (t >= d) ? sums[t - d] : 0;
        __syncthreads();
        sums[t] += v;
        __syncthreads();
    }
    if (t < 1000) {
        int run = (t == 0) ? 0 : sums[t - 1];
        #pragma unroll
        for (int i = 0; i < 20; i++) {
            g_off[base + i] = run;
            g_cur[base + i] = run;
            run += g_cnt[base + i];
        }
        if (t == 999) g_off[NN] = run;
    }
}
__global__ void scatter_k(const int* __restrict__ ei) {
    int e = blockIdx.x * blockDim.x + threadIdx.x;
    if (e >= E2T) return;
    int src, dst;
    if (e < EE) { src = ei[e]; dst = ei[EE + e]; }
    else        { src = e - EE; dst = src; }
    int pos = atomicAdd(&g_cur[dst], 1);
    g_srcs[pos] = src;
}

// ---------------- head-split packed attention -------------------------------
// Work item = (node, head-pair). One warp handles 2 heads = 128 channels;
// lane: sub = lane>>4 selects head within pair, li = lane&15 -> 4 channels.
// Per edge: ONE LDG.128 per lane, 16-lane logit reduce (4 shfls), private den/acc.
__device__ __forceinline__ float edge_logit2(const uint64_t* tp, const uint64_t* rp,
                                             const uint64_t* lp) {
    uint64_t s2 = 0ull;
    #pragma unroll
    for (int i = 0; i < 2; i++) {
        uint64_t u = fma2v(lp[i], C_ONE2, rp[i]);         // xl + xr
        uint64_t au = u & C_ABS;                           // |u|
        uint64_t w = fma2v(au, C_04, 0ull);                // 0.4|u|
        w = fma2v(u, C_06, w);                             // 0.6u + 0.4|u|
        ffma2(s2, tp[i], w);                               // att * lrelu
    }
    float2 sv = unpack2(s2);
    return sv.x + sv.y;
}

__device__ __forceinline__ void load_half(int src, int c0, uint64_t* lp) {
    ulonglong2 u = *(const ulonglong2*)(g_xl + (size_t)src * HIDC + c0);
    lp[0] = u.x; lp[1] = u.y;
}

__global__ void __launch_bounds__(256)
attn_fused_k(const float* __restrict__ att, const float* __restrict__ bias,
             float* __restrict__ dout, int to_gh, int lsel) {
    int lane = threadIdx.x & 31;
    int sub = lane >> 4;          // head within pair
    int li  = lane & 15;          // 4-channel slice within head
    float* obase = to_gh ? g_h : dout;

    int w;
    if (lane == 0) w = atomicAdd(&g_ctr[lsel], 1);
    w = __shfl_sync(0xffffffffu, w, 0);

    while (w < 2 * NN) {
        int nw;
        if (lane == 0) nw = atomicAdd(&g_ctr[lsel], 1);   // prefetch next ticket

        int n = w >> 1;
        int head = (w & 1) * 2 + sub;
        int c0 = head * 64 + li * 4;

        uint64_t tp[2], rp[2];
        {
            ulonglong2 a2 = *(const ulonglong2*)(att + c0);
            tp[0] = a2.x; tp[1] = a2.y;
            ulonglong2 r2 = *(const ulonglong2*)(g_xr + (size_t)n * HIDC + c0);
            rp[0] = r2.x; rp[1] = r2.y;
        }

        uint64_t acc[2] = {0ull, 0ull};
        float den = 0.f;

        int jb = g_off[n], je = g_off[n + 1];
        for (int base = jb; base < je; base += 32) {
            int rem = je - base;
            int cnt = rem < 32 ? rem : 32;
            int midx = 0;
            if (base + lane < je) midx = g_srcs[base + lane];

            int j = 0;
            // ---- 4-edge groups: 4 independent logit/shfl/exp chains ----
            for (; j + 3 < cnt; j += 4) {
                int sa = __shfl_sync(0xffffffffu, midx, j);
                int sb = __shfl_sync(0xffffffffu, midx, j + 1);
                int sc = __shfl_sync(0xffffffffu, midx, j + 2);
                int sd = __shfl_sync(0xffffffffu, midx, j + 3);
                uint64_t lpa[2], lpb[2], lpc[2], lpd[2];
                load_half(sa, c0, lpa);
                load_half(sb, c0, lpb);
                load_half(sc, c0, lpc);
                load_half(sd, c0, lpd);

                float s0 = edge_logit2(tp, rp, lpa);
                float s1 = edge_logit2(tp, rp, lpb);
                float s2 = edge_logit2(tp, rp, lpc);
                float s3 = edge_logit2(tp, rp, lpd);

                s0 += __shfl_xor_sync(0xffffffffu, s0, 1);
                s1 += __shfl_xor_sync(0xffffffffu, s1, 1);
                s2 += __shfl_xor_sync(0xffffffffu, s2, 1);
                s3 += __shfl_xor_sync(0xffffffffu, s3, 1);
                s0 += __shfl_xor_sync(0xffffffffu, s0, 2);
                s1 += __shfl_xor_sync(0xffffffffu, s1, 2);
                s2 += __shfl_xor_sync(0xffffffffu, s2, 2);
                s3 += __shfl_xor_sync(0xffffffffu, s3, 2);
                s0 += __shfl_xor_sync(0xffffffffu, s0, 4);
                s1 += __shfl_xor_sync(0xffffffffu, s1, 4);
                s2 += __shfl_xor_sync(0xffffffffu, s2, 4);
                s3 += __shfl_xor_sync(0xffffffffu, s3, 4);
                s0 += __shfl_xor_sync(0xffffffffu, s0, 8);
                s1 += __shfl_xor_sync(0xffffffffu, s1, 8);
                s2 += __shfl_xor_sync(0xffffffffu, s2, 8);
                s3 += __shfl_xor_sync(0xffffffffu, s3, 8);

                float e0 = __expf(s0), e1 = __expf(s1);
                float e2 = __expf(s2), e3 = __expf(s3);
                den += (e0 + e1) + (e2 + e3);
                uint64_t e02 = pack2(e0), e12 = pack2(e1);
                uint64_t e22 = pack2(e2), e32 = pack2(e3);
                #pragma unroll
                for (int q = 0; q < 2; q++) {
                    ffma2(acc[q], e02, lpa[q]);
                    ffma2(acc[q], e12, lpb[q]);
                    ffma2(acc[q], e22, lpc[q]);
                    ffma2(acc[q], e32, lpd[q]);
                }
            }
            // ---- remainder ----
            for (; j < cnt; j++) {
                int sa = __shfl_sync(0xffffffffu, midx, j);
                uint64_t lpa[2];
                load_half(sa, c0, lpa);
                float s0 = edge_logit2(tp, rp, lpa);
                s0 += __shfl_xor_sync(0xffffffffu, s0, 1);
                s0 += __shfl_xor_sync(0xffffffffu, s0, 2);
                s0 += __shfl_xor_sync(0xffffffffu, s0, 4);
                s0 += __shfl_xor_sync(0xffffffffu, s0, 8);
                float e0 = __expf(s0);
                den += e0;
                uint64_t e02 = pack2(e0);
                #pragma unroll
                for (int q = 0; q < 2; q++) ffma2(acc[q], e02, lpa[q]);
            }
        }

        float rd = 1.f / den;
        float4 bv = *(const float4*)(bias + c0);
        float2 a0 = unpack2(acc[0]), a1 = unpack2(acc[1]);
        float4 o;
        o.x = fmaxf(a0.x * rd + bv.x, 0.f);
        o.y = fmaxf(a0.y * rd + bv.y, 0.f);
        o.z = fmaxf(a1.x * rd + bv.z, 0.f);
        o.w = fmaxf(a1.y * rd + bv.w, 0.f);
        *(float4*)(obase + (size_t)n * HIDC + c0) = o;

        w = __shfl_sync(0xffffffffu, nw, 0);
    }
}

// ---------------- host ----------------
extern "C" void kernel_launch(void* const* d_in, const int* in_sizes, int n_in,
                              void* d_out, int out_size) {
    const float* x     = (const float*)d_in[0];
    const int*   ei    = (const int*)  d_in[1];
    const float* Wl1   = (const float*)d_in[2];
    const float* bl1   = (const float*)d_in[3];
    const float* Wr1   = (const float*)d_in[4];
    const float* br1   = (const float*)d_in[5];
    const float* att1  = (const float*)d_in[6];
    const float* bias1 = (const float*)d_in[7];
    const float* Wl2   = (const float*)d_in[8];
    const float* bl2   = (const float*)d_in[9];
    const float* Wr2   = (const float*)d_in[10];
    const float* br2   = (const float*)d_in[11];
    const float* att2  = (const float*)d_in[12];
    const float* bias2 = (const float*)d_in[13];
    float* out = (float*)d_out;

    const int TB = 256;
    dim3 gg((NN + 95) / 96, 4);                   // 209 x 4 = 836 blocks
    const int awb = 148 * 4;

    // CSR build (shared by both layers)
    hist_init_k<<<(NN + TB - 1) / TB, TB>>>();
    hist_k<<<(EE + TB - 1) / TB, TB>>>(ei);
    scan_k<<<1, 1024>>>();
    scatter_k<<<(E2T + TB - 1) / TB, TB>>>(ei);

    // ----- layer 1 (x -> g_h) -----
    gemm_dual<<<gg, TB>>>(x, 0, Wl1, bl1, Wr1, br1);
    attn_fused_k<<<awb, TB>>>(att1, bias1, out, 1, 0);

    // ----- layer 2 (g_h -> d_out) -----
    gemm_dual<<<gg, TB>>>(x, 1, Wl2, bl2, Wr2, br2);
    attn_fused_k<<<awb, TB>>>(att2, bias2, out, 0, 1);
}

// round 14
// speedup vs baseline: 1.0505x; 1.0505x over previous
#include <cuda_runtime.h>
#include <cstdint>

#define NN    20000
#define EE    320000
#define E2T   340000          // EE + NN self loops
#define HIDC  256
#define NH    4
#define NEG   0.2f

// ---------------- device scratch (static, no allocation) ----------------
__device__ __align__(16) float g_xl[NN * HIDC];
__device__ __align__(16) float g_xr[NN * HIDC];
__device__ __align__(16) float g_h [NN * HIDC];
__device__ int g_cnt[NN];
__device__ int g_off[NN + 1];
__device__ int g_cur[NN];
__device__ int g_srcs[E2T];
__device__ int g_ctr[2];          // dynamic node tickets, one per layer

// packed fp32 FMA
__device__ __forceinline__ void ffma2(uint64_t& d, uint64_t a, uint64_t b) {
    asm("fma.rn.f32x2 %0, %1, %2, %0;" : "+l"(d) : "l"(a), "l"(b));
}
__device__ __forceinline__ uint64_t fma2v(uint64_t a, uint64_t b, uint64_t c) {
    uint64_t d;
    asm("fma.rn.f32x2 %0, %1, %2, %3;" : "=l"(d) : "l"(a), "l"(b), "l"(c));
    return d;
}
__device__ __forceinline__ float2 unpack2(uint64_t v) {
    uint32_t lo, hi;
    asm("mov.b64 {%0, %1}, %2;" : "=r"(lo), "=r"(hi) : "l"(v));
    return make_float2(__uint_as_float(lo), __uint_as_float(hi));
}
__device__ __forceinline__ uint64_t pack2(float x) {
    uint64_t d;
    asm("mov.b64 %0, {%1, %1};" : "=l"(d) : "r"(__float_as_uint(x)));
    return d;
}
#define C_ONE2  0x3F8000003F800000ull   // (1.0f, 1.0f)
#define C_06    0x3F19999A3F19999Aull   // (0.6f, 0.6f)
#define C_04    0x3ECCCCCD3ECCCCCDull   // (0.4f, 0.4f)
#define C_ABS   0x7FFFFFFF7FFFFFFFull

// ---------------- fused dual GEMM (xl & xr), fp32 via fma.rn.f32x2 ----------------
// CTA tile 96(M) x 128(N), 256 threads, 6x8 outputs/thread.
__global__ void __launch_bounds__(256, 2)
gemm_dual(const float* __restrict__ Ain, int a_is_gh,
          const float* __restrict__ Wl, const float* __restrict__ bl,
          const float* __restrict__ Wr, const float* __restrict__ br) {
    __shared__ float As[16][100];   // [k][m] 96 + pad 4
    __shared__ float Bs[16][136];   // [k][n] 128 + pad 8

    const float* A = a_is_gh ? g_h : Ain;
    int by = blockIdx.y;
    int sel = by >> 1;
    const float* W    = sel ? Wr : Wl;
    const float* bias = sel ? br : bl;
    float*       C    = sel ? g_xr : g_xl;
    int bn = (by & 1) * 128;
    int bm = blockIdx.x * 96;

    int tid = threadIdx.x;
    int tx = tid & 15, ty = tid >> 4;
    bool aload = tid < 192;
    int e0 = tid * 2, e1 = tid * 2 + 1;
    int r0 = e0 >> 2, q0 = e0 & 3;
    int r1 = e1 >> 2, q1 = e1 & 3;
    int w_r = tid >> 4, w_c = tid & 15;

    uint64_t acc[6][4];
    #pragma unroll
    for (int i = 0; i < 6; i++)
        #pragma unroll
        for (int q = 0; q < 4; q++) acc[i][q] = 0ull;

    float4 pa0 = make_float4(0.f, 0.f, 0.f, 0.f);
    float4 pa1 = make_float4(0.f, 0.f, 0.f, 0.f);
    float4 pb[2];
    if (aload) {
        if (bm + r0 < NN) pa0 = *(const float4*)(A + (size_t)(bm + r0) * 256 + q0 * 4);
        if (bm + r1 < NN) pa1 = *(const float4*)(A + (size_t)(bm + r1) * 256 + q1 * 4);
    }
    #pragma unroll
    for (int h = 0; h < 2; h++)
        pb[h] = *(const float4*)(W + (size_t)w_r * 256 + bn + h * 64 + w_c * 4);

    for (int k0 = 0; k0 < 256; k0 += 16) {
        if (aload) {
            As[q0 * 4 + 0][r0] = pa0.x;
            As[q0 * 4 + 1][r0] = pa0.y;
            As[q0 * 4 + 2][r0] = pa0.z;
            As[q0 * 4 + 3][r0] = pa0.w;
            As[q1 * 4 + 0][r1] = pa1.x;
            As[q1 * 4 + 1][r1] = pa1.y;
            As[q1 * 4 + 2][r1] = pa1.z;
            As[q1 * 4 + 3][r1] = pa1.w;
        }
        #pragma unroll
        for (int h = 0; h < 2; h++)
            *(float4*)&Bs[w_r][h * 64 + w_c * 4] = pb[h];
        __syncthreads();

        if (k0 < 240) {
            int kn = k0 + 16;
            if (aload) {
                if (bm + r0 < NN)
                    pa0 = *(const float4*)(A + (size_t)(bm + r0) * 256 + kn + q0 * 4);
                if (bm + r1 < NN)
                    pa1 = *(const float4*)(A + (size_t)(bm + r1) * 256 + kn + q1 * 4);
            }
            #pragma unroll
            for (int h = 0; h < 2; h++)
                pb[h] = *(const float4*)(W + (size_t)(kn + w_r) * 256 + bn + h * 64 + w_c * 4);
        }

        #pragma unroll
        for (int k = 0; k < 16; k++) {
            float2 af0 = *(const float2*)&As[k][ty * 6];
            float2 af1 = *(const float2*)&As[k][ty * 6 + 2];
            float2 af2 = *(const float2*)&As[k][ty * 6 + 4];
            ulonglong2 u = *(const ulonglong2*)&Bs[k][tx * 4];
            ulonglong2 v = *(const ulonglong2*)&Bs[k][64 + tx * 4];
            uint64_t ar[6];
            ar[0] = pack2(af0.x); ar[1] = pack2(af0.y);
            ar[2] = pack2(af1.x); ar[3] = pack2(af1.y);
            ar[4] = pack2(af2.x); ar[5] = pack2(af2.y);
            #pragma unroll
            for (int i = 0; i < 6; i++) {
                ffma2(acc[i][0], ar[i], u.x);
                ffma2(acc[i][1], ar[i], u.y);
                ffma2(acc[i][2], ar[i], v.x);
                ffma2(acc[i][3], ar[i], v.y);
            }
        }
        __syncthreads();
    }

    float4 bv0 = *(const float4*)(bias + bn + tx * 4);
    float4 bv1 = *(const float4*)(bias + bn + 64 + tx * 4);
    #pragma unroll
    for (int i = 0; i < 6; i++) {
        int row = bm + ty * 6 + i;
        if (row < NN) {
            float2 c0 = unpack2(acc[i][0]), c1 = unpack2(acc[i][1]);
            float2 c2 = unpack2(acc[i][2]), c3 = unpack2(acc[i][3]);
            *(float4*)(C + (size_t)row * 256 + bn + tx * 4) =
                make_float4(c0.x + bv0.x, c0.y + bv0.y, c1.x + bv0.z, c1.y + bv0.w);
            *(float4*)(C + (size_t)row * 256 + bn + 64 + tx * 4) =
                make_float4(c2.x + bv1.x, c2.y + bv1.y, c3.x + bv1.z, c3.y + bv1.w);
        }
    }
}

// ---------------- CSR build (once per launch; edges shared by both layers) ----
__global__ void hist_init_k() {
    int i = blockIdx.x * blockDim.x + threadIdx.x;
    if (i < NN) g_cnt[i] = 1;      // self loop pre-counted
    if (i < 2)  g_ctr[i] = 0;
}
__global__ void hist_k(const int* __restrict__ ei) {
    int e = blockIdx.x * blockDim.x + threadIdx.x;
    if (e < EE) atomicAdd(&g_cnt[ei[EE + e]], 1);
}
__global__ void scan_k() {
    __shared__ int sums[1024];
    int t = threadIdx.x;
    int base = t * 20;
    int s = 0;
    if (t < 1000) {
        #pragma unroll
        for (int i = 0; i < 20; i++) s += g_cnt[base + i];
    }
    sums[t] = s;
    __syncthreads();
    #pragma unroll
    for (int d = 1; d < 1024; d <<= 1) {
        int v = (t >= d) ? sums[t - d] : 0;
        __syncthreads();
        sums[t] += v;
        __syncthreads();
    }
    if (t < 1000) {
        int run = (t == 0) ? 0 : sums[t - 1];
        #pragma unroll
        for (int i = 0; i < 20; i++) {
            g_off[base + i] = run;
            g_cur[base + i] = run;
            run += g_cnt[base + i];
        }
        if (t == 999) g_off[NN] = run;
    }
}
__global__ void scatter_k(const int* __restrict__ ei) {
    int e = blockIdx.x * blockDim.x + threadIdx.x;
    if (e >= E2T) return;
    int src, dst;
    if (e < EE) { src = ei[e]; dst = ei[EE + e]; }
    else        { src = e - EE; dst = src; }
    int pos = atomicAdd(&g_cur[dst], 1);
    g_srcs[pos] = src;
}

// ---------------- packed-f32x2 attention core ---------------------------------
__device__ __forceinline__ float edge_logit(const uint64_t* tp, const uint64_t* rp,
                                            const uint64_t* lp) {
    uint64_t s2 = 0ull;
    #pragma unroll
    for (int i = 0; i < 4; i++) {
        uint64_t u = fma2v(lp[i], C_ONE2, rp[i]);         // xl + xr
        uint64_t au = u & C_ABS;                           // |u| (alu pipe)
        uint64_t w = fma2v(au, C_04, 0ull);                // 0.4|u|
        w = fma2v(u, C_06, w);                             // 0.6u + 0.4|u|
        ffma2(s2, tp[i], w);                               // att * lrelu
    }
    float2 sv = unpack2(s2);
    return sv.x + sv.y;
}

__device__ __forceinline__ void load_row(int src, int c0, uint64_t* lp) {
    const ulonglong2* x2 = (const ulonglong2*)(g_xl + (size_t)src * HIDC + c0);
    ulonglong2 u0 = x2[0], u1 = x2[1];
    lp[0] = u0.x; lp[1] = u0.y; lp[2] = u1.x; lp[3] = u1.y;
}

__global__ void __launch_bounds__(256)
attn_fused_k(const float* __restrict__ att, const float* __restrict__ bias,
             float* __restrict__ dout, int to_gh, int lsel) {
    int lane = threadIdx.x & 31;
    int c0 = lane * 8;
    int head = lane >> 3;

    uint64_t tp[4];
    {
        const ulonglong2* a2 = (const ulonglong2*)(att + head * 64 + (lane & 7) * 8);
        ulonglong2 u0 = a2[0], u1 = a2[1];
        tp[0] = u0.x; tp[1] = u0.y; tp[2] = u1.x; tp[3] = u1.y;
    }
    const float4* b4 = (const float4*)(bias + c0);
    float4 b0 = b4[0], b1 = b4[1];
    float* obase = to_gh ? g_h : dout;

    int n;
    if (lane == 0) n = atomicAdd(&g_ctr[lsel], 1);
    n = __shfl_sync(0xffffffffu, n, 0);

    while (n < NN) {
        int nn;
        if (lane == 0) nn = atomicAdd(&g_ctr[lsel], 1);   // prefetch next ticket

        uint64_t rp[4];
        {
            const ulonglong2* r2 = (const ulonglong2*)(g_xr + (size_t)n * HIDC + c0);
            ulonglong2 u0 = r2[0], u1 = r2[1];
            rp[0] = u0.x; rp[1] = u0.y; rp[2] = u1.x; rp[3] = u1.y;
        }

        uint64_t acc[4] = {0ull, 0ull, 0ull, 0ull};
        float den = 0.f;

        int jb = g_off[n], je = g_off[n + 1];
        for (int base = jb; base < je; base += 32) {
            int rem = je - base;
            int cnt = rem < 32 ? rem : 32;
            int midx = 0;
            if (base + lane < je) midx = g_srcs[base + lane];

            int j = 0;
            // ---- 8-edge groups: 8 independent logit/shfl/exp chains, 16 loads in flight
            for (; j + 7 < cnt; j += 8) {
                uint64_t lp[8][4];
                float s[8];
                #pragma unroll
                for (int u = 0; u < 8; u++) {
                    int sidx = __shfl_sync(0xffffffffu, midx, j + u);
                    load_row(sidx, c0, lp[u]);
                }
                #pragma unroll
                for (int u = 0; u < 8; u++) s[u] = edge_logit(tp, rp, lp[u]);
                #pragma unroll
                for (int u = 0; u < 8; u++) s[u] += __shfl_xor_sync(0xffffffffu, s[u], 1);
                #pragma unroll
                for (int u = 0; u < 8; u++) s[u] += __shfl_xor_sync(0xffffffffu, s[u], 2);
                #pragma unroll
                for (int u = 0; u < 8; u++) s[u] += __shfl_xor_sync(0xffffffffu, s[u], 4);
                #pragma unroll
                for (int u = 0; u < 8; u++) {
                    float e = __expf(s[u]);
                    den += e;
                    uint64_t e2 = pack2(e);
                    ffma2(acc[0], e2, lp[u][0]);
                    ffma2(acc[1], e2, lp[u][1]);
                    ffma2(acc[2], e2, lp[u][2]);
                    ffma2(acc[3], e2, lp[u][3]);
                }
            }
            // ---- 4-edge groups ----
            for (; j + 3 < cnt; j += 4) {
                uint64_t lp[4][4];
                float s[4];
                #pragma unroll
                for (int u = 0; u < 4; u++) {
                    int sidx = __shfl_sync(0xffffffffu, midx, j + u);
                    load_row(sidx, c0, lp[u]);
                }
                #pragma unroll
                for (int u = 0; u < 4; u++) s[u] = edge_logit(tp, rp, lp[u]);
                #pragma unroll
                for (int u = 0; u < 4; u++) s[u] += __shfl_xor_sync(0xffffffffu, s[u], 1);
                #pragma unroll
                for (int u = 0; u < 4; u++) s[u] += __shfl_xor_sync(0xffffffffu, s[u], 2);
                #pragma unroll
                for (int u = 0; u < 4; u++) s[u] += __shfl_xor_sync(0xffffffffu, s[u], 4);
                #pragma unroll
                for (int u = 0; u < 4; u++) {
                    float e = __expf(s[u]);
                    den += e;
                    uint64_t e2 = pack2(e);
                    ffma2(acc[0], e2, lp[u][0]);
                    ffma2(acc[1], e2, lp[u][1]);
                    ffma2(acc[2], e2, lp[u][2]);
                    ffma2(acc[3], e2, lp[u][3]);
                }
            }
            // ---- remainder ----
            for (; j < cnt; j++) {
                int sa = __shfl_sync(0xffffffffu, midx, j);
                uint64_t lpa[4];
                load_row(sa, c0, lpa);
                float s0 = edge_logit(tp, rp, lpa);
                s0 += __shfl_xor_sync(0xffffffffu, s0, 1);
                s0 += __shfl_xor_sync(0xffffffffu, s0, 2);
                s0 += __shfl_xor_sync(0xffffffffu, s0, 4);
                float e0 = __expf(s0);
                den += e0;
                uint64_t e02 = pack2(e0);
                #pragma unroll
                for (int q = 0; q < 4; q++) ffma2(acc[q], e02, lpa[q]);
            }
        }

        float rd = 1.f / den;
        float2 a0 = unpack2(acc[0]), a1 = unpack2(acc[1]);
        float2 a2 = unpack2(acc[2]), a3 = unpack2(acc[3]);
        float4 o0, o1;
        o0.x = fmaxf(a0.x * rd + b0.x, 0.f);
        o0.y = fmaxf(a0.y * rd + b0.y, 0.f);
        o0.z = fmaxf(a1.x * rd + b0.z, 0.f);
        o0.w = fmaxf(a1.y * rd + b0.w, 0.f);
        o1.x = fmaxf(a2.x * rd + b1.x, 0.f);
        o1.y = fmaxf(a2.y * rd + b1.y, 0.f);
        o1.z = fmaxf(a3.x * rd + b1.z, 0.f);
        o1.w = fmaxf(a3.y * rd + b1.w, 0.f);

        float4* outp = (float4*)(obase + (size_t)n * HIDC + c0);
        outp[0] = o0;
        outp[1] = o1;

        n = __shfl_sync(0xffffffffu, nn, 0);
    }
}

// ---------------- host ----------------
extern "C" void kernel_launch(void* const* d_in, const int* in_sizes, int n_in,
                              void* d_out, int out_size) {
    const float* x     = (const float*)d_in[0];
    const int*   ei    = (const int*)  d_in[1];
    const float* Wl1   = (const float*)d_in[2];
    const float* bl1   = (const float*)d_in[3];
    const float* Wr1   = (const float*)d_in[4];
    const float* br1   = (const float*)d_in[5];
    const float* att1  = (const float*)d_in[6];
    const float* bias1 = (const float*)d_in[7];
    const float* Wl2   = (const float*)d_in[8];
    const float* bl2   = (const float*)d_in[9];
    const float* Wr2   = (const float*)d_in[10];
    const float* br2   = (const float*)d_in[11];
    const float* att2  = (const float*)d_in[12];
    const float* bias2 = (const float*)d_in[13];
    float* out = (float*)d_out;

    const int TB = 256;
    dim3 gg((NN + 95) / 96, 4);                   // 209 x 4 = 836 blocks
    const int awb = 148 * 4;

    // CSR build (shared by both layers)
    hist_init_k<<<(NN + TB - 1) / TB, TB>>>();
    hist_k<<<(EE + TB - 1) / TB, TB>>>(ei);
    scan_k<<<1, 1024>>>();
    scatter_k<<<(E2T + TB - 1) / TB, TB>>>(ei);

    // ----- layer 1 (x -> g_h) -----
    gemm_dual<<<gg, TB>>>(x, 0, Wl1, bl1, Wr1, br1);
    attn_fused_k<<<awb, TB>>>(att1, bias1, out, 1, 0);

    // ----- layer 2 (g_h -> d_out) -----
    gemm_dual<<<gg, TB>>>(x, 1, Wl2, bl2, Wr2, br2);
    attn_fused_k<<<awb, TB>>>(att2, bias2, out, 0, 1);
}

// round 15
// speedup vs baseline: 1.0615x; 1.0104x over previous
#include <cuda_runtime.h>
#include <cstdint>

#define NN    20000
#define EE    320000
#define E2T   340000          // EE + NN self loops
#define HIDC  256
#define NH    4
#define NEG   0.2f

// ---------------- device scratch (static, no allocation) ----------------
__device__ __align__(16) float g_xl[NN * HIDC];
__device__ __align__(16) float g_xr[NN * HIDC];
__device__ __align__(16) float g_h [NN * HIDC];
__device__ int g_cnt[NN];
__device__ int g_off[NN + 1];
__device__ int g_cur[NN];
__device__ int g_srcs[E2T];
__device__ int g_ctr[2];          // dynamic node tickets, one per layer

// packed fp32 FMA
__device__ __forceinline__ void ffma2(uint64_t& d, uint64_t a, uint64_t b) {
    asm("fma.rn.f32x2 %0, %1, %2, %0;" : "+l"(d) : "l"(a), "l"(b));
}
__device__ __forceinline__ uint64_t fma2v(uint64_t a, uint64_t b, uint64_t c) {
    uint64_t d;
    asm("fma.rn.f32x2 %0, %1, %2, %3;" : "=l"(d) : "l"(a), "l"(b), "l"(c));
    return d;
}
__device__ __forceinline__ float2 unpack2(uint64_t v) {
    uint32_t lo, hi;
    asm("mov.b64 {%0, %1}, %2;" : "=r"(lo), "=r"(hi) : "l"(v));
    return make_float2(__uint_as_float(lo), __uint_as_float(hi));
}
__device__ __forceinline__ uint64_t pack2(float x) {
    uint64_t d;
    asm("mov.b64 %0, {%1, %1};" : "=l"(d) : "r"(__float_as_uint(x)));
    return d;
}
#define C_ONE2  0x3F8000003F800000ull   // (1.0f, 1.0f)
#define C_06    0x3F19999A3F19999Aull   // (0.6f, 0.6f)
#define C_04    0x3ECCCCCD3ECCCCCDull   // (0.4f, 0.4f)
#define C_ABS   0x7FFFFFFF7FFFFFFFull

// ---------------- fused dual GEMM (xl & xr), fp32 via fma.rn.f32x2 ----------------
// CTA tile 96(M) x 128(N), 256 threads, 6x8 outputs/thread.
// Double-buffered smem: one __syncthreads per k-chunk; staging of chunk c+1
// overlaps compute of chunk c.
__global__ void __launch_bounds__(256, 2)
gemm_dual(const float* __restrict__ Ain, int a_is_gh,
          const float* __restrict__ Wl, const float* __restrict__ bl,
          const float* __restrict__ Wr, const float* __restrict__ br) {
    __shared__ float As[2][16][100];   // [buf][k][m] 96 + pad 4
    __shared__ float Bs[2][16][136];   // [buf][k][n] 128 + pad 8

    const float* A = a_is_gh ? g_h : Ain;
    int by = blockIdx.y;
    int sel = by >> 1;
    const float* W    = sel ? Wr : Wl;
    const float* bias = sel ? br : bl;
    float*       C    = sel ? g_xr : g_xl;
    int bn = (by & 1) * 128;
    int bm = blockIdx.x * 96;

    int tid = threadIdx.x;
    int tx = tid & 15, ty = tid >> 4;
    bool aload = tid < 192;
    int e0 = tid * 2, e1 = tid * 2 + 1;
    int r0 = e0 >> 2, q0 = e0 & 3;
    int r1 = e1 >> 2, q1 = e1 & 3;
    int w_r = tid >> 4, w_c = tid & 15;
    bool a0ok = aload && (bm + r0 < NN);
    bool a1ok = aload && (bm + r1 < NN);

    uint64_t acc[6][4];
    #pragma unroll
    for (int i = 0; i < 6; i++)
        #pragma unroll
        for (int q = 0; q < 4; q++) acc[i][q] = 0ull;

    float4 pa0 = make_float4(0.f, 0.f, 0.f, 0.f);
    float4 pa1 = make_float4(0.f, 0.f, 0.f, 0.f);
    float4 pb[2];
    if (a0ok) pa0 = *(const float4*)(A + (size_t)(bm + r0) * 256 + q0 * 4);
    if (a1ok) pa1 = *(const float4*)(A + (size_t)(bm + r1) * 256 + q1 * 4);
    #pragma unroll
    for (int h = 0; h < 2; h++)
        pb[h] = *(const float4*)(W + (size_t)w_r * 256 + bn + h * 64 + w_c * 4);

    // stage chunk 0 into buffer 0
    if (aload) {
        As[0][q0 * 4 + 0][r0] = pa0.x;
        As[0][q0 * 4 + 1][r0] = pa0.y;
        As[0][q0 * 4 + 2][r0] = pa0.z;
        As[0][q0 * 4 + 3][r0] = pa0.w;
        As[0][q1 * 4 + 0][r1] = pa1.x;
        As[0][q1 * 4 + 1][r1] = pa1.y;
        As[0][q1 * 4 + 2][r1] = pa1.z;
        As[0][q1 * 4 + 3][r1] = pa1.w;
    }
    #pragma unroll
    for (int h = 0; h < 2; h++)
        *(float4*)&Bs[0][w_r][h * 64 + w_c * 4] = pb[h];
    __syncthreads();

    #pragma unroll 1
    for (int c = 0; c < 16; c++) {
        int cur = c & 1, nxt = cur ^ 1;
        if (c < 15) {
            int kn = (c + 1) * 16;
            if (a0ok) pa0 = *(const float4*)(A + (size_t)(bm + r0) * 256 + kn + q0 * 4);
            if (a1ok) pa1 = *(const float4*)(A + (size_t)(bm + r1) * 256 + kn + q1 * 4);
            #pragma unroll
            for (int h = 0; h < 2; h++)
                pb[h] = *(const float4*)(W + (size_t)(kn + w_r) * 256 + bn + h * 64 + w_c * 4);
        }

        #pragma unroll
        for (int k = 0; k < 16; k++) {
            float2 af0 = *(const float2*)&As[cur][k][ty * 6];
            float2 af1 = *(const float2*)&As[cur][k][ty * 6 + 2];
            float2 af2 = *(const float2*)&As[cur][k][ty * 6 + 4];
            ulonglong2 u = *(const ulonglong2*)&Bs[cur][k][tx * 4];
            ulonglong2 v = *(const ulonglong2*)&Bs[cur][k][64 + tx * 4];
            uint64_t ar[6];
            ar[0] = pack2(af0.x); ar[1] = pack2(af0.y);
            ar[2] = pack2(af1.x); ar[3] = pack2(af1.y);
            ar[4] = pack2(af2.x); ar[5] = pack2(af2.y);
            #pragma unroll
            for (int i = 0; i < 6; i++) {
                ffma2(acc[i][0], ar[i], u.x);
                ffma2(acc[i][1], ar[i], u.y);
                ffma2(acc[i][2], ar[i], v.x);
                ffma2(acc[i][3], ar[i], v.y);
            }
        }

        if (c < 15) {
            if (aload) {
                As[nxt][q0 * 4 + 0][r0] = pa0.x;
                As[nxt][q0 * 4 + 1][r0] = pa0.y;
                As[nxt][q0 * 4 + 2][r0] = pa0.z;
                As[nxt][q0 * 4 + 3][r0] = pa0.w;
                As[nxt][q1 * 4 + 0][r1] = pa1.x;
                As[nxt][q1 * 4 + 1][r1] = pa1.y;
                As[nxt][q1 * 4 + 2][r1] = pa1.z;
                As[nxt][q1 * 4 + 3][r1] = pa1.w;
            }
            #pragma unroll
            for (int h = 0; h < 2; h++)
                *(float4*)&Bs[nxt][w_r][h * 64 + w_c * 4] = pb[h];
            __syncthreads();
        }
    }

    float4 bv0 = *(const float4*)(bias + bn + tx * 4);
    float4 bv1 = *(const float4*)(bias + bn + 64 + tx * 4);
    #pragma unroll
    for (int i = 0; i < 6; i++) {
        int row = bm + ty * 6 + i;
        if (row < NN) {
            float2 c0 = unpack2(acc[i][0]), c1 = unpack2(acc[i][1]);
            float2 c2 = unpack2(acc[i][2]), c3 = unpack2(acc[i][3]);
            *(float4*)(C + (size_t)row * 256 + bn + tx * 4) =
                make_float4(c0.x + bv0.x, c0.y + bv0.y, c1.x + bv0.z, c1.y + bv0.w);
            *(float4*)(C + (size_t)row * 256 + bn + 64 + tx * 4) =
                make_float4(c2.x + bv1.x, c2.y + bv1.y, c3.x + bv1.z, c3.y + bv1.w);
        }
    }
}

// ---------------- CSR build (once per launch; edges shared by both layers) ----
__global__ void hist_k(const int* __restrict__ ei) {
    int i = blockIdx.x * blockDim.x + threadIdx.x;
    if (i < NN) g_cnt[i] = 1;          // self loop pre-counted (init)
    if (i < 2)  g_ctr[i] = 0;
    // grid-wide barrier not needed: counts for node v only touched via atomics
    // after init... but init and atomics race across blocks. Keep separate phase:
}
__global__ void hist2_k(const int* __restrict__ ei) {
    int e = blockIdx.x * blockDim.x + threadIdx.x;
    if (e < EE) atomicAdd(&g_cnt[ei[EE + e]], 1);
}
__global__ void scan_k() {
    __shared__ int sums[1024];
    int t = threadIdx.x;
    int base = t * 20;
    int s = 0;
    if (t < 1000) {
        #pragma unroll
        for (int i = 0; i < 20; i++) s += g_cnt[base + i];
    }
    sums[t] = s;
    __syncthreads();
    #pragma unroll
    for (int d = 1; d < 1024; d <<= 1) {
        int v = (t >= d) ? sums[t - d] : 0;
        __syncthreads();
        sums[t] += v;
        __syncthreads();
    }
    if (t < 1000) {
        int run = (t == 0) ? 0 : sums[t - 1];
        #pragma unroll
        for (int i = 0; i < 20; i++) {
            g_off[base + i] = run;
            g_cur[base + i] = run;
            run += g_cnt[base + i];
        }
        if (t == 999) g_off[NN] = run;
    }
}
__global__ void scatter_k(const int* __restrict__ ei) {
    int e = blockIdx.x * blockDim.x + threadIdx.x;
    if (e >= E2T) return;
    int src, dst;
    if (e < EE) { src = ei[e]; dst = ei[EE + e]; }
    else        { src = e - EE; dst = src; }
    int pos = atomicAdd(&g_cur[dst], 1);
    g_srcs[pos] = src;
}

// ---------------- packed-f32x2 attention core (R12 form: 4-edge groups) -------
__device__ __forceinline__ float edge_logit(const uint64_t* tp, const uint64_t* rp,
                                            const uint64_t* lp) {
    uint64_t s2 = 0ull;
    #pragma unroll
    for (int i = 0; i < 4; i++) {
        uint64_t u = fma2v(lp[i], C_ONE2, rp[i]);         // xl + xr
        uint64_t au = u & C_ABS;                           // |u| (alu pipe)
        uint64_t w = fma2v(au, C_04, 0ull);                // 0.4|u|
        w = fma2v(u, C_06, w);                             // 0.6u + 0.4|u|
        ffma2(s2, tp[i], w);                               // att * lrelu
    }
    float2 sv = unpack2(s2);
    return sv.x + sv.y;
}

__device__ __forceinline__ void load_row(int src, int c0, uint64_t* lp) {
    const ulonglong2* x2 = (const ulonglong2*)(g_xl + (size_t)src * HIDC + c0);
    ulonglong2 u0 = x2[0], u1 = x2[1];
    lp[0] = u0.x; lp[1] = u0.y; lp[2] = u1.x; lp[3] = u1.y;
}

__global__ void __launch_bounds__(256)
attn_fused_k(const float* __restrict__ att, const float* __restrict__ bias,
             float* __restrict__ dout, int to_gh, int lsel) {
    int lane = threadIdx.x & 31;
    int c0 = lane * 8;
    int head = lane >> 3;

    uint64_t tp[4];
    {
        const ulonglong2* a2 = (const ulonglong2*)(att + head * 64 + (lane & 7) * 8);
        ulonglong2 u0 = a2[0], u1 = a2[1];
        tp[0] = u0.x; tp[1] = u0.y; tp[2] = u1.x; tp[3] = u1.y;
    }
    const float4* b4 = (const float4*)(bias + c0);
    float4 b0 = b4[0], b1 = b4[1];
    float* obase = to_gh ? g_h : dout;

    int n;
    if (lane == 0) n = atomicAdd(&g_ctr[lsel], 1);
    n = __shfl_sync(0xffffffffu, n, 0);

    while (n < NN) {
        int nn;
        if (lane == 0) nn = atomicAdd(&g_ctr[lsel], 1);   // prefetch next ticket

        uint64_t rp[4];
        {
            const ulonglong2* r2 = (const ulonglong2*)(g_xr + (size_t)n * HIDC + c0);
            ulonglong2 u0 = r2[0], u1 = r2[1];
            rp[0] = u0.x; rp[1] = u0.y; rp[2] = u1.x; rp[3] = u1.y;
        }

        uint64_t acc[4] = {0ull, 0ull, 0ull, 0ull};
        float den = 0.f;

        int jb = g_off[n], je = g_off[n + 1];
        for (int base = jb; base < je; base += 32) {
            int rem = je - base;
            int cnt = rem < 32 ? rem : 32;
            int midx = 0;
            if (base + lane < je) midx = g_srcs[base + lane];

            int j = 0;
            // ---- 4-edge groups: 4 independent logit/shfl/exp chains ----
            for (; j + 3 < cnt; j += 4) {
                int sa = __shfl_sync(0xffffffffu, midx, j);
                int sb = __shfl_sync(0xffffffffu, midx, j + 1);
                int sc = __shfl_sync(0xffffffffu, midx, j + 2);
                int sd = __shfl_sync(0xffffffffu, midx, j + 3);
                uint64_t lpa[4], lpb[4], lpc[4], lpd[4];
                load_row(sa, c0, lpa);
                load_row(sb, c0, lpb);
                load_row(sc, c0, lpc);
                load_row(sd, c0, lpd);

                float s0 = edge_logit(tp, rp, lpa);
                float s1 = edge_logit(tp, rp, lpb);
                float s2 = edge_logit(tp, rp, lpc);
                float s3 = edge_logit(tp, rp, lpd);

                s0 += __shfl_xor_sync(0xffffffffu, s0, 1);
                s1 += __shfl_xor_sync(0xffffffffu, s1, 1);
                s2 += __shfl_xor_sync(0xffffffffu, s2, 1);
                s3 += __shfl_xor_sync(0xffffffffu, s3, 1);
                s0 += __shfl_xor_sync(0xffffffffu, s0, 2);
                s1 += __shfl_xor_sync(0xffffffffu, s1, 2);
                s2 += __shfl_xor_sync(0xffffffffu, s2, 2);
                s3 += __shfl_xor_sync(0xffffffffu, s3, 2);
                s0 += __shfl_xor_sync(0xffffffffu, s0, 4);
                s1 += __shfl_xor_sync(0xffffffffu, s1, 4);
                s2 += __shfl_xor_sync(0xffffffffu, s2, 4);
                s3 += __shfl_xor_sync(0xffffffffu, s3, 4);

                float e0 = __expf(s0), e1 = __expf(s1);
                float e2 = __expf(s2), e3 = __expf(s3);
                den += (e0 + e1) + (e2 + e3);
                uint64_t e02 = pack2(e0), e12 = pack2(e1);
                uint64_t e22 = pack2(e2), e32 = pack2(e3);
                #pragma unroll
                for (int q = 0; q < 4; q++) {
                    ffma2(acc[q], e02, lpa[q]);
                    ffma2(acc[q], e12, lpb[q]);
                    ffma2(acc[q], e22, lpc[q]);
                    ffma2(acc[q], e32, lpd[q]);
                }
            }
            // ---- remainder ----
            for (; j < cnt; j++) {
                int sa = __shfl_sync(0xffffffffu, midx, j);
                uint64_t lpa[4];
                load_row(sa, c0, lpa);
                float s0 = edge_logit(tp, rp, lpa);
                s0 += __shfl_xor_sync(0xffffffffu, s0, 1);
                s0 += __shfl_xor_sync(0xffffffffu, s0, 2);
                s0 += __shfl_xor_sync(0xffffffffu, s0, 4);
                float e0 = __expf(s0);
                den += e0;
                uint64_t e02 = pack2(e0);
                #pragma unroll
                for (int q = 0; q < 4; q++) ffma2(acc[q], e02, lpa[q]);
            }
        }

        float rd = 1.f / den;
        float2 a0 = unpack2(acc[0]), a1 = unpack2(acc[1]);
        float2 a2 = unpack2(acc[2]), a3 = unpack2(acc[3]);
        float4 o0, o1;
        o0.x = fmaxf(a0.x * rd + b0.x, 0.f);
        o0.y = fmaxf(a0.y * rd + b0.y, 0.f);
        o0.z = fmaxf(a1.x * rd + b0.z, 0.f);
        o0.w = fmaxf(a1.y * rd + b0.w, 0.f);
        o1.x = fmaxf(a2.x * rd + b1.x, 0.f);
        o1.y = fmaxf(a2.y * rd + b1.y, 0.f);
        o1.z = fmaxf(a3.x * rd + b1.z, 0.f);
        o1.w = fmaxf(a3.y * rd + b1.w, 0.f);

        float4* outp = (float4*)(obase + (size_t)n * HIDC + c0);
        outp[0] = o0;
        outp[1] = o1;

        n = __shfl_sync(0xffffffffu, nn, 0);
    }
}

// ---------------- host ----------------
extern "C" void kernel_launch(void* const* d_in, const int* in_sizes, int n_in,
                              void* d_out, int out_size) {
    const float* x     = (const float*)d_in[0];
    const int*   ei    = (const int*)  d_in[1];
    const float* Wl1   = (const float*)d_in[2];
    const float* bl1   = (const float*)d_in[3];
    const float* Wr1   = (const float*)d_in[4];
    const float* br1   = (const float*)d_in[5];
    const float* att1  = (const float*)d_in[6];
    const float* bias1 = (const float*)d_in[7];
    const float* Wl2   = (const float*)d_in[8];
    const float* bl2   = (const float*)d_in[9];
    const float* Wr2   = (const float*)d_in[10];
    const float* br2   = (const float*)d_in[11];
    const float* att2  = (const float*)d_in[12];
    const float* bias2 = (const float*)d_in[13];
    float* out = (float*)d_out;

    const int TB = 256;
    dim3 gg((NN + 95) / 96, 4);                   // 209 x 4 = 836 blocks
    const int awb = 148 * 4;

    // CSR build (shared by both layers)
    hist_k<<<(NN + TB - 1) / TB, TB>>>(ei);
    hist2_k<<<(EE + TB - 1) / TB, TB>>>(ei);
    scan_k<<<1, 1024>>>();
    scatter_k<<<(E2T + TB - 1) / TB, TB>>>(ei);

    // ----- layer 1 (x -> g_h) -----
    gemm_dual<<<gg, TB>>>(x, 0, Wl1, bl1, Wr1, br1);
    attn_fused_k<<<awb, TB>>>(att1, bias1, out, 1, 0);

    // ----- layer 2 (g_h -> d_out) -----
    gemm_dual<<<gg, TB>>>(x, 1, Wl2, bl2, Wr2, br2);
    attn_fused_k<<<awb, TB>>>(att2, bias2, out, 0, 1);
}

// round 16
// speedup vs baseline: 1.1471x; 1.0807x over previous
#include <cuda_runtime.h>
#include <cstdint>

#define NN    20000
#define EE    320000
#define E2T   340000          // EE + NN self loops
#define HIDC  256
#define NH    4
#define NEG   0.2f

// ---------------- device scratch (static, no allocation) ----------------
__device__ __align__(16) float g_xl[NN * HIDC];
__device__ __align__(16) float g_xr[NN * HIDC];
__device__ __align__(16) float g_h [NN * HIDC];
__device__ int g_cnt[NN];
__device__ int g_off[NN + 1];
__device__ int g_cur[NN];
__device__ int g_srcs[E2T];
__device__ int g_ctr[2];          // dynamic node tickets, one per layer

// packed fp32 FMA
__device__ __forceinline__ void ffma2(uint64_t& d, uint64_t a, uint64_t b) {
    asm("fma.rn.f32x2 %0, %1, %2, %0;" : "+l"(d) : "l"(a), "l"(b));
}
__device__ __forceinline__ uint64_t fma2v(uint64_t a, uint64_t b, uint64_t c) {
    uint64_t d;
    asm("fma.rn.f32x2 %0, %1, %2, %3;" : "=l"(d) : "l"(a), "l"(b), "l"(c));
    return d;
}
__device__ __forceinline__ float2 unpack2(uint64_t v) {
    uint32_t lo, hi;
    asm("mov.b64 {%0, %1}, %2;" : "=r"(lo), "=r"(hi) : "l"(v));
    return make_float2(__uint_as_float(lo), __uint_as_float(hi));
}
__device__ __forceinline__ uint64_t pack2(float x) {
    uint64_t d;
    asm("mov.b64 %0, {%1, %1};" : "=l"(d) : "r"(__float_as_uint(x)));
    return d;
}
#define C_ONE2  0x3F8000003F800000ull   // (1.0f, 1.0f)
#define C_06    0x3F19999A3F19999Aull   // (0.6f, 0.6f)
#define C_04    0x3ECCCCCD3ECCCCCDull   // (0.4f, 0.4f)
#define C_ABS   0x7FFFFFFF7FFFFFFFull

// ---------------- fused dual GEMM (xl & xr), fp32 via fma.rn.f32x2 ----------------
// CTA tile 96(M) x 128(N), 256 threads, 6x8 outputs/thread.
__global__ void __launch_bounds__(256, 2)
gemm_dual(const float* __restrict__ Ain, int a_is_gh,
          const float* __restrict__ Wl, const float* __restrict__ bl,
          const float* __restrict__ Wr, const float* __restrict__ br) {
    __shared__ float As[16][100];   // [k][m] 96 + pad 4
    __shared__ float Bs[16][136];   // [k][n] 128 + pad 8

    const float* A = a_is_gh ? g_h : Ain;
    int by = blockIdx.y;
    int sel = by >> 1;
    const float* W    = sel ? Wr : Wl;
    const float* bias = sel ? br : bl;
    float*       C    = sel ? g_xr : g_xl;
    int bn = (by & 1) * 128;
    int bm = blockIdx.x * 96;

    int tid = threadIdx.x;
    int tx = tid & 15, ty = tid >> 4;
    bool aload = tid < 192;
    int e0 = tid * 2, e1 = tid * 2 + 1;
    int r0 = e0 >> 2, q0 = e0 & 3;
    int r1 = e1 >> 2, q1 = e1 & 3;
    int w_r = tid >> 4, w_c = tid & 15;

    uint64_t acc[6][4];
    #pragma unroll
    for (int i = 0; i < 6; i++)
        #pragma unroll
        for (int q = 0; q < 4; q++) acc[i][q] = 0ull;

    float4 pa0 = make_float4(0.f, 0.f, 0.f, 0.f);
    float4 pa1 = make_float4(0.f, 0.f, 0.f, 0.f);
    float4 pb[2];
    if (aload) {
        if (bm + r0 < NN) pa0 = *(const float4*)(A + (size_t)(bm + r0) * 256 + q0 * 4);
        if (bm + r1 < NN) pa1 = *(const float4*)(A + (size_t)(bm + r1) * 256 + q1 * 4);
    }
    #pragma unroll
    for (int h = 0; h < 2; h++)
        pb[h] = *(const float4*)(W + (size_t)w_r * 256 + bn + h * 64 + w_c * 4);

    for (int k0 = 0; k0 < 256; k0 += 16) {
        if (aload) {
            As[q0 * 4 + 0][r0] = pa0.x;
            As[q0 * 4 + 1][r0] = pa0.y;
            As[q0 * 4 + 2][r0] = pa0.z;
            As[q0 * 4 + 3][r0] = pa0.w;
            As[q1 * 4 + 0][r1] = pa1.x;
            As[q1 * 4 + 1][r1] = pa1.y;
            As[q1 * 4 + 2][r1] = pa1.z;
            As[q1 * 4 + 3][r1] = pa1.w;
        }
        #pragma unroll
        for (int h = 0; h < 2; h++)
            *(float4*)&Bs[w_r][h * 64 + w_c * 4] = pb[h];
        __syncthreads();

        if (k0 < 240) {
            int kn = k0 + 16;
            if (aload) {
                if (bm + r0 < NN)
                    pa0 = *(const float4*)(A + (size_t)(bm + r0) * 256 + kn + q0 * 4);
                if (bm + r1 < NN)
                    pa1 = *(const float4*)(A + (size_t)(bm + r1) * 256 + kn + q1 * 4);
            }
            #pragma unroll
            for (int h = 0; h < 2; h++)
                pb[h] = *(const float4*)(W + (size_t)(kn + w_r) * 256 + bn + h * 64 + w_c * 4);
        }

        #pragma unroll
        for (int k = 0; k < 16; k++) {
            float2 af0 = *(const float2*)&As[k][ty * 6];
            float2 af1 = *(const float2*)&As[k][ty * 6 + 2];
            float2 af2 = *(const float2*)&As[k][ty * 6 + 4];
            ulonglong2 u = *(const ulonglong2*)&Bs[k][tx * 4];
            ulonglong2 v = *(const ulonglong2*)&Bs[k][64 + tx * 4];
            uint64_t ar[6];
            ar[0] = pack2(af0.x); ar[1] = pack2(af0.y);
            ar[2] = pack2(af1.x); ar[3] = pack2(af1.y);
            ar[4] = pack2(af2.x); ar[5] = pack2(af2.y);
            #pragma unroll
            for (int i = 0; i < 6; i++) {
                ffma2(acc[i][0], ar[i], u.x);
                ffma2(acc[i][1], ar[i], u.y);
                ffma2(acc[i][2], ar[i], v.x);
                ffma2(acc[i][3], ar[i], v.y);
            }
        }
        __syncthreads();
    }

    float4 bv0 = *(const float4*)(bias + bn + tx * 4);
    float4 bv1 = *(const float4*)(bias + bn + 64 + tx * 4);
    #pragma unroll
    for (int i = 0; i < 6; i++) {
        int row = bm + ty * 6 + i;
        if (row < NN) {
            float2 c0 = unpack2(acc[i][0]), c1 = unpack2(acc[i][1]);
            float2 c2 = unpack2(acc[i][2]), c3 = unpack2(acc[i][3]);
            *(float4*)(C + (size_t)row * 256 + bn + tx * 4) =
                make_float4(c0.x + bv0.x, c0.y + bv0.y, c1.x + bv0.z, c1.y + bv0.w);
            *(float4*)(C + (size_t)row * 256 + bn + 64 + tx * 4) =
                make_float4(c2.x + bv1.x, c2.y + bv1.y, c3.x + bv1.z, c3.y + bv1.w);
        }
    }
}

// ---------------- CSR build (once per launch; edges shared by both layers) ----
__global__ void hist_init_k() {
    int i = blockIdx.x * blockDim.x + threadIdx.x;
    if (i < NN) g_cnt[i] = 1;      // self loop pre-counted
    if (i < 2)  g_ctr[i] = 0;
}
__global__ void hist_k(const int* __restrict__ ei) {
    int e = blockIdx.x * blockDim.x + threadIdx.x;
    if (e < EE) atomicAdd(&g_cnt[ei[EE + e]], 1);
}
__global__ void scan_k() {
    __shared__ int sums[1024];
    int t = threadIdx.x;
    int base = t * 20;
    int s = 0;
    if (t < 1000) {
        #pragma unroll
        for (int i = 0; i < 20; i++) s += g_cnt[base + i];
    }
    sums[t] = s;
    __syncthreads();
    #pragma unroll
    for (int d = 1; d < 1024; d <<= 1) {
        int v = (t >= d) ? sums[t - d] : 0;
        __syncthreads();
        sums[t] += v;
        __syncthreads();
    }
    if (t < 1000) {
        int run = (t == 0) ? 0 : sums[t - 1];
        #pragma unroll
        for (int i = 0; i < 20; i++) {
            g_off[base + i] = run;
            g_cur[base + i] = run;
            run += g_cnt[base + i];
        }
        if (t == 999) g_off[NN] = run;
    }
}
__global__ void scatter_k(const int* __restrict__ ei) {
    int e = blockIdx.x * blockDim.x + threadIdx.x;
    if (e >= E2T) return;
    int src, dst;
    if (e < EE) { src = ei[e]; dst = ei[EE + e]; }
    else        { src = e - EE; dst = src; }
    int pos = atomicAdd(&g_cur[dst], 1);
    g_srcs[pos] = src;
}

// ---------------- packed-f32x2 attention core (4-edge groups) ------------------
__device__ __forceinline__ float edge_logit(const uint64_t* tp, const uint64_t* rp,
                                            const uint64_t* lp) {
    uint64_t s2 = 0ull;
    #pragma unroll
    for (int i = 0; i < 4; i++) {
        uint64_t u = fma2v(lp[i], C_ONE2, rp[i]);         // xl + xr
        uint64_t au = u & C_ABS;                           // |u| (alu pipe)
        uint64_t w = fma2v(au, C_04, 0ull);                // 0.4|u|
        w = fma2v(u, C_06, w);                             // 0.6u + 0.4|u|
        ffma2(s2, tp[i], w);                               // att * lrelu
    }
    float2 sv = unpack2(s2);
    return sv.x + sv.y;
}

__device__ __forceinline__ void load_row(int src, int c0, uint64_t* lp) {
    const ulonglong2* x2 = (const ulonglong2*)(g_xl + (size_t)src * HIDC + c0);
    ulonglong2 u0 = x2[0], u1 = x2[1];
    lp[0] = u0.x; lp[1] = u0.y; lp[2] = u1.x; lp[3] = u1.y;
}

__global__ void __launch_bounds__(256)
attn_fused_k(const float* __restrict__ att, const float* __restrict__ bias,
             float* __restrict__ dout, int to_gh, int lsel) {
    int lane = threadIdx.x & 31;
    int c0 = lane * 8;
    int head = lane >> 3;

    uint64_t tp[4];
    {
        const ulonglong2* a2 = (const ulonglong2*)(att + head * 64 + (lane & 7) * 8);
        ulonglong2 u0 = a2[0], u1 = a2[1];
        tp[0] = u0.x; tp[1] = u0.y; tp[2] = u1.x; tp[3] = u1.y;
    }
    const float4* b4 = (const float4*)(bias + c0);
    float4 b0 = b4[0], b1 = b4[1];
    float* obase = to_gh ? g_h : dout;

    int n;
    if (lane == 0) n = atomicAdd(&g_ctr[lsel], 1);
    n = __shfl_sync(0xffffffffu, n, 0);

    while (n < NN) {
        int nn;
        if (lane == 0) nn = atomicAdd(&g_ctr[lsel], 1);   // prefetch next ticket

        uint64_t rp[4];
        {
            const ulonglong2* r2 = (const ulonglong2*)(g_xr + (size_t)n * HIDC + c0);
            ulonglong2 u0 = r2[0], u1 = r2[1];
            rp[0] = u0.x; rp[1] = u0.y; rp[2] = u1.x; rp[3] = u1.y;
        }

        uint64_t acc[4] = {0ull, 0ull, 0ull, 0ull};
        float den = 0.f;

        int jb = g_off[n], je = g_off[n + 1];
        for (int base = jb; base < je; base += 32) {
            int rem = je - base;
            int cnt = rem < 32 ? rem : 32;
            int midx = 0;
            if (base + lane < je) midx = g_srcs[base + lane];

            int j = 0;
            for (; j + 3 < cnt; j += 4) {
                int sa = __shfl_sync(0xffffffffu, midx, j);
                int sb = __shfl_sync(0xffffffffu, midx, j + 1);
                int sc = __shfl_sync(0xffffffffu, midx, j + 2);
                int sd = __shfl_sync(0xffffffffu, midx, j + 3);
                uint64_t lpa[4], lpb[4], lpc[4], lpd[4];
                load_row(sa, c0, lpa);
                load_row(sb, c0, lpb);
                load_row(sc, c0, lpc);
                load_row(sd, c0, lpd);

                float s0 = edge_logit(tp, rp, lpa);
                float s1 = edge_logit(tp, rp, lpb);
                float s2 = edge_logit(tp, rp, lpc);
                float s3 = edge_logit(tp, rp, lpd);

                s0 += __shfl_xor_sync(0xffffffffu, s0, 1);
                s1 += __shfl_xor_sync(0xffffffffu, s1, 1);
                s2 += __shfl_xor_sync(0xffffffffu, s2, 1);
                s3 += __shfl_xor_sync(0xffffffffu, s3, 1);
                s0 += __shfl_xor_sync(0xffffffffu, s0, 2);
                s1 += __shfl_xor_sync(0xffffffffu, s1, 2);
                s2 += __shfl_xor_sync(0xffffffffu, s2, 2);
                s3 += __shfl_xor_sync(0xffffffffu, s3, 2);
                s0 += __shfl_xor_sync(0xffffffffu, s0, 4);
                s1 += __shfl_xor_sync(0xffffffffu, s1, 4);
                s2 += __shfl_xor_sync(0xffffffffu, s2, 4);
                s3 += __shfl_xor_sync(0xffffffffu, s3, 4);

                float e0 = __expf(s0), e1 = __expf(s1);
                float e2 = __expf(s2), e3 = __expf(s3);
                den += (e0 + e1) + (e2 + e3);
                uint64_t e02 = pack2(e0), e12 = pack2(e1);
                uint64_t e22 = pack2(e2), e32 = pack2(e3);
                #pragma unroll
                for (int q = 0; q < 4; q++) {
                    ffma2(acc[q], e02, lpa[q]);
                    ffma2(acc[q], e12, lpb[q]);
                    ffma2(acc[q], e22, lpc[q]);
                    ffma2(acc[q], e32, lpd[q]);
                }
            }
            for (; j < cnt; j++) {
                int sa = __shfl_sync(0xffffffffu, midx, j);
                uint64_t lpa[4];
                load_row(sa, c0, lpa);
                float s0 = edge_logit(tp, rp, lpa);
                s0 += __shfl_xor_sync(0xffffffffu, s0, 1);
                s0 += __shfl_xor_sync(0xffffffffu, s0, 2);
                s0 += __shfl_xor_sync(0xffffffffu, s0, 4);
                float e0 = __expf(s0);
                den += e0;
                uint64_t e02 = pack2(e0);
                #pragma unroll
                for (int q = 0; q < 4; q++) ffma2(acc[q], e02, lpa[q]);
            }
        }

        float rd = 1.f / den;
        float2 a0 = unpack2(acc[0]), a1 = unpack2(acc[1]);
        float2 a2 = unpack2(acc[2]), a3 = unpack2(acc[3]);
        float4 o0, o1;
        o0.x = fmaxf(a0.x * rd + b0.x, 0.f);
        o0.y = fmaxf(a0.y * rd + b0.y, 0.f);
        o0.z = fmaxf(a1.x * rd + b0.z, 0.f);
        o0.w = fmaxf(a1.y * rd + b0.w, 0.f);
        o1.x = fmaxf(a2.x * rd + b1.x, 0.f);
        o1.y = fmaxf(a2.y * rd + b1.y, 0.f);
        o1.z = fmaxf(a3.x * rd + b1.z, 0.f);
        o1.w = fmaxf(a3.y * rd + b1.w, 0.f);

        float4* outp = (float4*)(obase + (size_t)n * HIDC + c0);
        outp[0] = o0;
        outp[1] = o1;

        n = __shfl_sync(0xffffffffu, nn, 0);
    }
}

// ---------------- host ----------------
extern "C" void kernel_launch(void* const* d_in, const int* in_sizes, int n_in,
                              void* d_out, int out_size) {
    const float* x     = (const float*)d_in[0];
    const int*   ei    = (const int*)  d_in[1];
    const float* Wl1   = (const float*)d_in[2];
    const float* bl1   = (const float*)d_in[3];
    const float* Wr1   = (const float*)d_in[4];
    const float* br1   = (const float*)d_in[5];
    const float* att1  = (const float*)d_in[6];
    const float* bias1 = (const float*)d_in[7];
    const float* Wl2   = (const float*)d_in[8];
    const float* bl2   = (const float*)d_in[9];
    const float* Wr2   = (const float*)d_in[10];
    const float* br2   = (const float*)d_in[11];
    const float* att2  = (const float*)d_in[12];
    const float* bias2 = (const float*)d_in[13];
    float* out = (float*)d_out;

    const int TB = 256;
    dim3 gg((NN + 95) / 96, 4);                   // 209 x 4 = 836 blocks
    const int awb = 148 * 4;

    // Fork a side stream so the CSR build (independent of layer-1 GEMM) runs
    // concurrently with it in the captured graph. Stream/events are created
    // per call and intentionally NOT destroyed (destroying mid-capture would
    // invalidate the capture; these are host-side objects, no device memory).
    cudaStream_t s2;
    cudaStreamCreateWithFlags(&s2, cudaStreamNonBlocking);
    cudaEvent_t evFork, evJoin;
    cudaEventCreateWithFlags(&evFork, cudaEventDisableTiming);
    cudaEventCreateWithFlags(&evJoin, cudaEventDisableTiming);

    // fork: s2 depends on everything before this point on the main stream
    cudaEventRecord(evFork, 0);
    cudaStreamWaitEvent(s2, evFork, 0);

    // CSR build on side stream
    hist_init_k<<<(NN + TB - 1) / TB, TB, 0, s2>>>();
    hist_k<<<(EE + TB - 1) / TB, TB, 0, s2>>>(ei);
    scan_k<<<1, 1024, 0, s2>>>();
    scatter_k<<<(E2T + TB - 1) / TB, TB, 0, s2>>>(ei);
    cudaEventRecord(evJoin, s2);

    // layer-1 GEMM on main stream, concurrent with CSR build
    gemm_dual<<<gg, TB>>>(x, 0, Wl1, bl1, Wr1, br1);

    // join: attention needs both GEMM-1 output and the CSR
    cudaStreamWaitEvent(0, evJoin, 0);
    attn_fused_k<<<awb, TB>>>(att1, bias1, out, 1, 0);

    // ----- layer 2 (g_h -> d_out) -----
    gemm_dual<<<gg, TB>>>(x, 1, Wl2, bl2, Wr2, br2);
    attn_fused_k<<<awb, TB>>>(att2, bias2, out, 0, 1);
}